// round 11
// baseline (speedup 1.0000x reference)
#include <cuda_runtime.h>
#include <cuda_fp16.h>
#include <cstdint>

// ---------------------------------------------------------------------------
// Problem constants
// ---------------------------------------------------------------------------
#define B_     8
#define CIN    128
#define H_     64
#define W_     64
#define COUT   128
#define KH     4
#define KW     4
#define KK     16
#define HO     61
#define WO     61
#define PIX    (HO*WO)            // 3721
#define M_TOT  (B_*PIX)           // 29768
#define M_PAD  29824              // 233 * 128
#define MT     233                // M tiles of 128
#define KDIM   2048
#define NCHUNK 32                 // K chunks of 64 halves
#define NTASK  (M_TOT*KK)         // 476288

// ---------------------------------------------------------------------------
// Scratch (device globals; zero-initialized; pad rows of g_A stay 0 forever)
// ---------------------------------------------------------------------------
__device__ __half g_inT[(size_t)B_*H_*W_*CIN];     // NHWC input fp16, 8.4 MB
__device__ __half g_A[(size_t)M_PAD*KDIM];         // sampled matrix fp16
__device__ __half g_W2[(size_t)COUT*KDIM];         // flipped/reordered weights fp16
__device__ uint4  g_wdesc[NTASK];                  // per-(k,m): 4 broadcast half2 weights
__device__ uint2  g_adesc[NTASK];                  // per-(k,m): {addr00 bytes, dys<<16|dxs}

// ---------------------------------------------------------------------------
// Helpers
// ---------------------------------------------------------------------------
__device__ __forceinline__ uint32_t smem_to_u32(const void* smem_ptr) {
    uint32_t addr;
    asm("{ .reg .u64 tmp; cvta.to.shared.u64 tmp, %1; cvt.u32.u64 %0, tmp; }"
        : "=r"(addr) : "l"(smem_ptr));
    return addr;
}
__device__ __forceinline__ void cp_async16(uint32_t smem_addr, const void* gptr) {
    asm volatile("cp.async.cg.shared.global [%0], [%1], 16;\n"
                 :: "r"(smem_addr), "l"(gptr));
}
#define CP_COMMIT() asm volatile("cp.async.commit_group;\n" ::: "memory")
#define CP_WAIT0()  asm volatile("cp.async.wait_group 0;\n" ::: "memory")
#define CP_WAIT1()  asm volatile("cp.async.wait_group 1;\n" ::: "memory")

__device__ __forceinline__ void ldmatrix_x4(uint32_t* r, uint32_t addr) {
    asm volatile("ldmatrix.sync.aligned.m8n8.x4.shared.b16 {%0,%1,%2,%3}, [%4];"
                 : "=r"(r[0]), "=r"(r[1]), "=r"(r[2]), "=r"(r[3]) : "r"(addr));
}
__device__ __forceinline__ void mma16816(float* c, const uint32_t* a, const uint32_t* b) {
    asm volatile(
        "mma.sync.aligned.m16n8k16.row.col.f32.f16.f16.f32 "
        "{%0,%1,%2,%3}, {%4,%5,%6,%7}, {%8,%9}, {%0,%1,%2,%3};"
        : "+f"(c[0]), "+f"(c[1]), "+f"(c[2]), "+f"(c[3])
        : "r"(a[0]), "r"(a[1]), "r"(a[2]), "r"(a[3]), "r"(b[0]), "r"(b[1]));
}

// ---------------------------------------------------------------------------
// Kernel 1: NCHW(f32) -> NHWC(f16) transpose of input
// ---------------------------------------------------------------------------
__global__ void transpose_kernel(const float* __restrict__ in) {
    __shared__ float tile[32][33];
    int id = blockIdx.x;
    int bh = id >> 3;
    int t  = id & 7;
    int c0 = (t >> 1) * 32;
    int x0 = (t & 1) * 32;
    int b = bh >> 6, y = bh & 63;
    int tx = threadIdx.x, ty = threadIdx.y;

    const float* src = in + (((size_t)(b * CIN + c0) * H_ + y) * W_ + x0);
#pragma unroll
    for (int j = 0; j < 4; j++) {
        int c = ty * 4 + j;
        tile[c][tx] = src[(size_t)c * (H_ * W_) + tx];
    }
    __syncthreads();
    __half* dst = g_inT + (((size_t)(b * H_ + y) * W_ + x0) * CIN + c0);
#pragma unroll
    for (int j = 0; j < 4; j++) {
        int xi = ty * 4 + j;
        dst[(size_t)xi * CIN + tx] = __float2half(tile[tx][xi]);
    }
}

// ---------------------------------------------------------------------------
// Kernel 2: weight flip + reorder to W2[co][k*128+ci], fp16
// ---------------------------------------------------------------------------
__global__ void prep_weight_kernel(const float* __restrict__ w) {
    int idx = blockIdx.x * 256 + threadIdx.x;
    if (idx >= COUT * KDIM) return;
    int o  = idx >> 11;
    int kk = idx & 2047;
    int k  = kk >> 7;
    int ci = kk & 127;
    int ki = k >> 2, kj = k & 3;
    float val = w[(((size_t)o * CIN + ci) * KH + (KH - 1 - ki)) * KW + (KW - 1 - kj)];
    g_W2[idx] = __float2half(val);
}

// ---------------------------------------------------------------------------
// Kernel 2b: precompute descriptors (weights pre-broadcast as half2)
// tid = k*M_TOT + m
// ---------------------------------------------------------------------------
__global__ void precompute_kernel(const float* __restrict__ offset,
                                  const float* __restrict__ mask) {
    int tid = blockIdx.x * 256 + threadIdx.x;
    if (tid >= NTASK) return;
    int k = tid / M_TOT;
    int m = tid - k * M_TOT;
    int b   = m / PIX;
    int rem = m - b * PIX;
    int oy  = rem / WO;
    int ox  = rem - oy * WO;
    int ki = k >> 2, kj = k & 3;

    int obase = ((b * (2 * KK) + 2 * k) * HO + oy) * WO + ox;
    float dy  = __ldg(offset + obase);
    float dx  = __ldg(offset + obase + PIX);
    float msk = __ldg(mask + ((b * KK + k) * HO + oy) * WO + ox);

    float y = dy + (float)(ki + oy);
    float x = dx + (float)(kj + ox);
    float y0f = floorf(y), x0f = floorf(x);
    float wy = y - y0f, wx = x - x0f;
    int y0 = (int)y0f, x0 = (int)x0f;

    bool vy0 = (y0 >= 0) && (y0 < H_);
    bool vy1 = (y0 >= -1) && (y0 < H_ - 1);
    bool vx0 = (x0 >= 0) && (x0 < W_);
    bool vx1 = (x0 >= -1) && (x0 < W_ - 1);

    float w00 = (vy0 && vx0) ? (1.f - wy) * (1.f - wx) * msk : 0.f;
    float w01 = (vy0 && vx1) ? (1.f - wy) * wx * msk : 0.f;
    float w10 = (vy1 && vx0) ? wy * (1.f - wx) * msk : 0.f;
    float w11 = (vy1 && vx1) ? wy * wx * msk : 0.f;

    int y0c = min(max(y0, 0), H_ - 1);
    int y1c = min(max(y0 + 1, 0), H_ - 1);
    int x0c = min(max(x0, 0), W_ - 1);
    int x1c = min(max(x0 + 1, 0), W_ - 1);

    __half2 h00 = __half2half2(__float2half(w00));
    __half2 h01 = __half2half2(__float2half(w01));
    __half2 h10 = __half2half2(__float2half(w10));
    __half2 h11 = __half2half2(__float2half(w11));
    uint4 wd;
    wd.x = *reinterpret_cast<uint32_t*>(&h00);
    wd.y = *reinterpret_cast<uint32_t*>(&h01);
    wd.z = *reinterpret_cast<uint32_t*>(&h10);
    wd.w = *reinterpret_cast<uint32_t*>(&h11);
    g_wdesc[tid] = wd;

    uint32_t addr00 = (uint32_t)((y0c * W_ + x0c) * CIN * 2);
    uint32_t dxs = (uint32_t)((x1c - x0c) * CIN * 2);        // 0 or 256
    uint32_t dys = (uint32_t)((y1c - y0c) * W_ * CIN * 2);   // 0 or 16384
    uint2 ad;
    ad.x = addr00;
    ad.y = (dys << 16) | dxs;
    g_adesc[tid] = ad;
}

// ---------------------------------------------------------------------------
// Kernel 3: lean fp16 bilinear sampler -> A[m][k*128+ci]
// Block 512 = 16 warps; warp = tap k, 32 consecutive pixels.
// Inner body: 2 desc lds + 4 gathers + 8 HFMA2-class ops + 1 store.
// ---------------------------------------------------------------------------
__global__ __launch_bounds__(512) void sample_kernel() {
    __shared__ uint32_t pixbase[32];
    const int tid  = threadIdx.x;
    const int k    = tid >> 5;
    const int lane = tid & 31;
    const int m0   = blockIdx.x * 32;

    if (tid < 32) {
        int m = m0 + tid;
        pixbase[tid] = (m < M_TOT) ?
            (uint32_t)((m / PIX) * (H_ * W_ * CIN * 2)) : 0xFFFFFFFFu;
    }
    __syncthreads();

    const char* imgC = (const char*)g_inT + lane * 8;
    const int dbase  = k * M_TOT + m0;

#pragma unroll 4
    for (int i = 0; i < 32; ++i) {
        uint32_t ib = pixbase[i];
        if (ib == 0xFFFFFFFFu) continue;
        int m = m0 + i;

        uint4 wd = __ldg(&g_wdesc[dbase + i]);
        uint2 ad = __ldg(&g_adesc[dbase + i]);
        uint32_t a00 = ad.x;
        uint32_t dxs = ad.y & 0xFFFFu;
        uint32_t dys = ad.y >> 16;

        const char* p = imgC + ib;
        uint2 q00 = *(const uint2*)(p + a00);
        uint2 q01 = *(const uint2*)(p + a00 + dxs);
        uint2 q10 = *(const uint2*)(p + a00 + dys);
        uint2 q11 = *(const uint2*)(p + a00 + dys + dxs);

        __half2 W00 = *reinterpret_cast<__half2*>(&wd.x);
        __half2 W01 = *reinterpret_cast<__half2*>(&wd.y);
        __half2 W10 = *reinterpret_cast<__half2*>(&wd.z);
        __half2 W11 = *reinterpret_cast<__half2*>(&wd.w);

        __half2 r0 = __hmul2(W00, *reinterpret_cast<__half2*>(&q00.x));
        r0 = __hfma2(W01, *reinterpret_cast<__half2*>(&q01.x), r0);
        r0 = __hfma2(W10, *reinterpret_cast<__half2*>(&q10.x), r0);
        r0 = __hfma2(W11, *reinterpret_cast<__half2*>(&q11.x), r0);

        __half2 r1 = __hmul2(W00, *reinterpret_cast<__half2*>(&q00.y));
        r1 = __hfma2(W01, *reinterpret_cast<__half2*>(&q01.y), r1);
        r1 = __hfma2(W10, *reinterpret_cast<__half2*>(&q10.y), r1);
        r1 = __hfma2(W11, *reinterpret_cast<__half2*>(&q11.y), r1);

        uint2 packed;
        packed.x = *reinterpret_cast<uint32_t*>(&r0);
        packed.y = *reinterpret_cast<uint32_t*>(&r1);
        *reinterpret_cast<uint2*>(g_A + (size_t)m * KDIM + k * 128 + lane * 4) = packed;
    }
}

// ---------------------------------------------------------------------------
// Kernel 4: GEMM — 4 warps x 64x64 warp tiles (LDS-optimal), 128 thr/CTA.
// CTA 128x128, K-chunk 64, 3-stage cp.async.
// LDS per chunk: A 16KB*2 + B 16KB*2 + STS 32KB = 96KB (vs 128KB for 2x4).
// ---------------------------------------------------------------------------
#define STAGE_BYTES 32768
#define GEMM_SMEM   98304

__global__ void gemm_kernel(const float* __restrict__ bias,
                            float* __restrict__ out) {
    extern __shared__ char smem[];
    const uint32_t smem_base = smem_to_u32(smem);
    const int tid  = threadIdx.x;
    const int wid  = tid >> 5;
    const int lane = tid & 31;
    const int m0   = blockIdx.x * 128;
    const int m_warp = (wid >> 1) * 64;   // 0 or 64
    const int n_warp = (wid & 1) * 64;    // 0 or 64

    float acc[4][8][4];
#pragma unroll
    for (int i = 0; i < 4; i++)
#pragma unroll
        for (int j = 0; j < 8; j++)
#pragma unroll
            for (int r = 0; r < 4; r++) acc[i][j][r] = 0.f;

    auto load_chunk = [&](int kc, int s) {
        uint32_t base = smem_base + s * STAGE_BYTES;
#pragma unroll
        for (int i = 0; i < 8; i++) {
            int sidx = tid + i * 128;          // 0..1023
            int row  = sidx >> 3;
            int cj   = sidx & 7;
            uint32_t off = (uint32_t)(row * 128 + ((cj ^ (row & 7)) << 4));
            cp_async16(base + off,
                       g_A + (size_t)(m0 + row) * KDIM + kc * 64 + cj * 8);
            cp_async16(base + 16384 + off,
                       g_W2 + (size_t)row * KDIM + kc * 64 + cj * 8);
        }
        CP_COMMIT();
    };

    load_chunk(0, 0);
    load_chunk(1, 1);

    int s = 0;
    for (int kc = 0; kc < NCHUNK; ++kc) {
        if (kc == NCHUNK - 1) { CP_WAIT0(); } else { CP_WAIT1(); }
        __syncthreads();
        if (kc + 2 < NCHUNK) {
            int s2 = s + 2; if (s2 >= 3) s2 -= 3;
            load_chunk(kc + 2, s2);
        }

        uint32_t aBase = smem_base + s * STAGE_BYTES;
        uint32_t bBase = aBase + 16384;
#pragma unroll
        for (int ks = 0; ks < 4; ++ks) {
            uint32_t afrag[4][4];
#pragma unroll
            for (int mi = 0; mi < 4; mi++) {
                int row = m_warp + mi * 16 + (lane & 15);
                int ch  = 2 * ks + (lane >> 4);
                ldmatrix_x4(afrag[mi], aBase + row * 128 + ((ch ^ (row & 7)) << 4));
            }
            uint32_t bfrag[8][2];
#pragma unroll
            for (int nh = 0; nh < 4; nh++) {
                int row = n_warp + nh * 16 + ((lane >> 4) << 3) + (lane & 7);
                int ch  = 2 * ks + ((lane >> 3) & 1);
                uint32_t r4[4];
                ldmatrix_x4(r4, bBase + row * 128 + ((ch ^ (row & 7)) << 4));
                bfrag[nh * 2][0]     = r4[0];
                bfrag[nh * 2][1]     = r4[1];
                bfrag[nh * 2 + 1][0] = r4[2];
                bfrag[nh * 2 + 1][1] = r4[3];
            }
#pragma unroll
            for (int mi = 0; mi < 4; mi++)
#pragma unroll
                for (int ni = 0; ni < 8; ni++)
                    mma16816(acc[mi][ni], afrag[mi], bfrag[ni]);
        }
        if (++s == 3) s = 0;
    }

    // ---- epilogue: stage tile in smem [128][129] f32, then coalesced writes
    __syncthreads();
    float* so = reinterpret_cast<float*>(smem);
#pragma unroll
    for (int mi = 0; mi < 4; mi++) {
#pragma unroll
        for (int ni = 0; ni < 8; ni++) {
            int r0 = m_warp + mi * 16 + (lane >> 2);
            int c0 = n_warp + ni * 8 + (lane & 3) * 2;
            so[r0 * 129 + c0]           = acc[mi][ni][0];
            so[r0 * 129 + c0 + 1]       = acc[mi][ni][1];
            so[(r0 + 8) * 129 + c0]     = acc[mi][ni][2];
            so[(r0 + 8) * 129 + c0 + 1] = acc[mi][ni][3];
        }
    }
    __syncthreads();

    // thread = M row; loop over co: warp writes 32 consecutive m per step
    {
        int m = m0 + tid;
        bool valid = (m < M_TOT);
        int b   = valid ? (m / PIX) : 0;
        int rem = m - b * PIX;
        float* op = out + (size_t)b * (COUT * PIX) + rem;
        const float* srow = so + tid * 129;
#pragma unroll 8
        for (int co = 0; co < COUT; co++) {
            if (valid) op[(size_t)co * PIX] = srow[co] + __ldg(bias + co);
        }
    }
}

// ---------------------------------------------------------------------------
// Launch
// ---------------------------------------------------------------------------
extern "C" void kernel_launch(void* const* d_in, const int* in_sizes, int n_in,
                              void* d_out, int out_size) {
    const float* input  = (const float*)d_in[0];
    const float* offset = (const float*)d_in[1];
    const float* mask   = (const float*)d_in[2];
    const float* weight = (const float*)d_in[3];
    const float* bias   = (const float*)d_in[4];
    float* out = (float*)d_out;

    cudaFuncSetAttribute(gemm_kernel,
                         cudaFuncAttributeMaxDynamicSharedMemorySize, GEMM_SMEM);

    transpose_kernel<<<B_ * H_ * 8, dim3(32, 8)>>>(input);
    prep_weight_kernel<<<(COUT * KDIM + 255) / 256, 256>>>(weight);
    precompute_kernel<<<(NTASK + 255) / 256, 256>>>(offset, mask);
    sample_kernel<<<(M_TOT + 31) / 32, 512>>>();
    gemm_kernel<<<MT, 128, GEMM_SMEM>>>(bias, out);
}

// round 13
// speedup vs baseline: 1.0062x; 1.0062x over previous
#include <cuda_runtime.h>
#include <cuda_fp16.h>
#include <cstdint>

// ---------------------------------------------------------------------------
// Problem constants
// ---------------------------------------------------------------------------
#define B_     8
#define CIN    128
#define H_     64
#define W_     64
#define COUT   128
#define KH     4
#define KW     4
#define KK     16
#define HO     61
#define WO     61
#define PIX    (HO*WO)            // 3721
#define M_TOT  (B_*PIX)           // 29768
#define M_PAD  29952              // 117 * 256
#define MT     117                // M tiles of 256
#define KDIM   2048
#define NCHUNK 32                 // K chunks of 64 halves
#define NTASK  (M_TOT*KK)         // 476288

// ---------------------------------------------------------------------------
// Scratch (device globals; zero-initialized; pad rows of g_A stay 0 forever)
// ---------------------------------------------------------------------------
__device__ __half g_inT[(size_t)B_*H_*W_*CIN];     // NHWC input fp16, 8.4 MB
__device__ __half g_A[(size_t)M_PAD*KDIM];         // sampled matrix fp16
__device__ __half g_W2[(size_t)COUT*KDIM];         // flipped/reordered weights fp16
__device__ uint4  g_wdesc[NTASK];                  // per-(k,m): 4 broadcast half2 weights
__device__ uint2  g_adesc[NTASK];                  // per-(k,m): {addr00 bytes, dys<<16|dxs}

// ---------------------------------------------------------------------------
// Helpers
// ---------------------------------------------------------------------------
__device__ __forceinline__ uint32_t smem_to_u32(const void* smem_ptr) {
    uint32_t addr;
    asm("{ .reg .u64 tmp; cvta.to.shared.u64 tmp, %1; cvt.u32.u64 %0, tmp; }"
        : "=r"(addr) : "l"(smem_ptr));
    return addr;
}
__device__ __forceinline__ void cp_async16(uint32_t smem_addr, const void* gptr) {
    asm volatile("cp.async.cg.shared.global [%0], [%1], 16;\n"
                 :: "r"(smem_addr), "l"(gptr));
}
#define CP_COMMIT() asm volatile("cp.async.commit_group;\n" ::: "memory")
#define CP_WAIT0()  asm volatile("cp.async.wait_group 0;\n" ::: "memory")
#define CP_WAIT1()  asm volatile("cp.async.wait_group 1;\n" ::: "memory")

__device__ __forceinline__ void ldmatrix_x4(uint32_t* r, uint32_t addr) {
    asm volatile("ldmatrix.sync.aligned.m8n8.x4.shared.b16 {%0,%1,%2,%3}, [%4];"
                 : "=r"(r[0]), "=r"(r[1]), "=r"(r[2]), "=r"(r[3]) : "r"(addr));
}
__device__ __forceinline__ void mma16816(float* c, const uint32_t* a, const uint32_t* b) {
    asm volatile(
        "mma.sync.aligned.m16n8k16.row.col.f32.f16.f16.f32 "
        "{%0,%1,%2,%3}, {%4,%5,%6,%7}, {%8,%9}, {%0,%1,%2,%3};"
        : "+f"(c[0]), "+f"(c[1]), "+f"(c[2]), "+f"(c[3])
        : "r"(a[0]), "r"(a[1]), "r"(a[2]), "r"(a[3]), "r"(b[0]), "r"(b[1]));
}

// ---------------------------------------------------------------------------
// Kernel 1: NCHW(f32) -> NHWC(f16) transpose of input
// ---------------------------------------------------------------------------
__global__ void transpose_kernel(const float* __restrict__ in) {
    __shared__ float tile[32][33];
    int id = blockIdx.x;
    int bh = id >> 3;
    int t  = id & 7;
    int c0 = (t >> 1) * 32;
    int x0 = (t & 1) * 32;
    int b = bh >> 6, y = bh & 63;
    int tx = threadIdx.x, ty = threadIdx.y;

    const float* src = in + (((size_t)(b * CIN + c0) * H_ + y) * W_ + x0);
#pragma unroll
    for (int j = 0; j < 4; j++) {
        int c = ty * 4 + j;
        tile[c][tx] = src[(size_t)c * (H_ * W_) + tx];
    }
    __syncthreads();
    __half* dst = g_inT + (((size_t)(b * H_ + y) * W_ + x0) * CIN + c0);
#pragma unroll
    for (int j = 0; j < 4; j++) {
        int xi = ty * 4 + j;
        dst[(size_t)xi * CIN + tx] = __float2half(tile[tx][xi]);
    }
}

// ---------------------------------------------------------------------------
// Kernel 2: weight flip + reorder to W2[co][k*128+ci], fp16
// ---------------------------------------------------------------------------
__global__ void prep_weight_kernel(const float* __restrict__ w) {
    int idx = blockIdx.x * 256 + threadIdx.x;
    if (idx >= COUT * KDIM) return;
    int o  = idx >> 11;
    int kk = idx & 2047;
    int k  = kk >> 7;
    int ci = kk & 127;
    int ki = k >> 2, kj = k & 3;
    float val = w[(((size_t)o * CIN + ci) * KH + (KH - 1 - ki)) * KW + (KW - 1 - kj)];
    g_W2[idx] = __float2half(val);
}

// ---------------------------------------------------------------------------
// Kernel 2b: precompute descriptors (weights pre-broadcast as half2)
// ---------------------------------------------------------------------------
__global__ void precompute_kernel(const float* __restrict__ offset,
                                  const float* __restrict__ mask) {
    int tid = blockIdx.x * 256 + threadIdx.x;
    if (tid >= NTASK) return;
    int k = tid / M_TOT;
    int m = tid - k * M_TOT;
    int b   = m / PIX;
    int rem = m - b * PIX;
    int oy  = rem / WO;
    int ox  = rem - oy * WO;
    int ki = k >> 2, kj = k & 3;

    int obase = ((b * (2 * KK) + 2 * k) * HO + oy) * WO + ox;
    float dy  = __ldg(offset + obase);
    float dx  = __ldg(offset + obase + PIX);
    float msk = __ldg(mask + ((b * KK + k) * HO + oy) * WO + ox);

    float y = dy + (float)(ki + oy);
    float x = dx + (float)(kj + ox);
    float y0f = floorf(y), x0f = floorf(x);
    float wy = y - y0f, wx = x - x0f;
    int y0 = (int)y0f, x0 = (int)x0f;

    bool vy0 = (y0 >= 0) && (y0 < H_);
    bool vy1 = (y0 >= -1) && (y0 < H_ - 1);
    bool vx0 = (x0 >= 0) && (x0 < W_);
    bool vx1 = (x0 >= -1) && (x0 < W_ - 1);

    float w00 = (vy0 && vx0) ? (1.f - wy) * (1.f - wx) * msk : 0.f;
    float w01 = (vy0 && vx1) ? (1.f - wy) * wx * msk : 0.f;
    float w10 = (vy1 && vx0) ? wy * (1.f - wx) * msk : 0.f;
    float w11 = (vy1 && vx1) ? wy * wx * msk : 0.f;

    int y0c = min(max(y0, 0), H_ - 1);
    int y1c = min(max(y0 + 1, 0), H_ - 1);
    int x0c = min(max(x0, 0), W_ - 1);
    int x1c = min(max(x0 + 1, 0), W_ - 1);

    __half2 h00 = __half2half2(__float2half(w00));
    __half2 h01 = __half2half2(__float2half(w01));
    __half2 h10 = __half2half2(__float2half(w10));
    __half2 h11 = __half2half2(__float2half(w11));
    uint4 wd;
    wd.x = *reinterpret_cast<uint32_t*>(&h00);
    wd.y = *reinterpret_cast<uint32_t*>(&h01);
    wd.z = *reinterpret_cast<uint32_t*>(&h10);
    wd.w = *reinterpret_cast<uint32_t*>(&h11);
    g_wdesc[tid] = wd;

    uint32_t addr00 = (uint32_t)((y0c * W_ + x0c) * CIN * 2);
    uint32_t dxs = (uint32_t)((x1c - x0c) * CIN * 2);        // 0 or 256
    uint32_t dys = (uint32_t)((y1c - y0c) * W_ * CIN * 2);   // 0 or 16384
    uint2 ad;
    ad.x = addr00;
    ad.y = (dys << 16) | dxs;
    g_adesc[tid] = ad;
}

// ---------------------------------------------------------------------------
// Kernel 3: lean fp16 bilinear sampler, LDG.128 2-tasks-per-warp.
// Block 512 = 16 warps; warp = tap k; half-warp = one (pixel,tap) task.
// Per task: 1 desc pair + 2 LDG.128 (amortized 4->2) + 8 HFMA2 + 0.5 STG.128.
// ---------------------------------------------------------------------------
__global__ __launch_bounds__(512) void sample_kernel() {
    __shared__ uint32_t pixbase[32];
    const int tid  = threadIdx.x;
    const int k    = tid >> 5;
    const int lane = tid & 31;
    const int m0   = blockIdx.x * 32;

    if (tid < 32) {
        int m = m0 + tid;
        pixbase[tid] = (m < M_TOT) ?
            (uint32_t)((m / PIX) * (H_ * W_ * CIN * 2)) : 0xFFFFFFFFu;
    }
    __syncthreads();

    const int half  = lane >> 4;        // 0/1: which task of the pair
    const int lane8 = lane & 15;        // 16B slot within task
    const char* imgC = (const char*)g_inT + lane8 * 16;
    const int dbase  = k * M_TOT + m0;

#pragma unroll 4
    for (int i = 0; i < 32; i += 2) {
        int ii = i + half;
        uint32_t ib = pixbase[ii];
        bool valid = (ib != 0xFFFFFFFFu);
        uint32_t ibs = valid ? ib : 0u;

        uint4 wd = __ldg(&g_wdesc[dbase + ii]);
        uint2 ad = __ldg(&g_adesc[dbase + ii]);
        uint32_t a00 = ad.x;
        uint32_t dxs = ad.y & 0xFFFFu;
        uint32_t dys = ad.y >> 16;

        const char* p = imgC + ibs;
        uint4 q00 = *(const uint4*)(p + a00);
        uint4 q01 = *(const uint4*)(p + a00 + dxs);
        uint4 q10 = *(const uint4*)(p + a00 + dys);
        uint4 q11 = *(const uint4*)(p + a00 + dys + dxs);

        __half2 W00 = *reinterpret_cast<__half2*>(&wd.x);
        __half2 W01 = *reinterpret_cast<__half2*>(&wd.y);
        __half2 W10 = *reinterpret_cast<__half2*>(&wd.z);
        __half2 W11 = *reinterpret_cast<__half2*>(&wd.w);

        uint4 res;
        {
            __half2 r = __hmul2(W00, *reinterpret_cast<__half2*>(&q00.x));
            r = __hfma2(W01, *reinterpret_cast<__half2*>(&q01.x), r);
            r = __hfma2(W10, *reinterpret_cast<__half2*>(&q10.x), r);
            r = __hfma2(W11, *reinterpret_cast<__half2*>(&q11.x), r);
            res.x = *reinterpret_cast<uint32_t*>(&r);
        }
        {
            __half2 r = __hmul2(W00, *reinterpret_cast<__half2*>(&q00.y));
            r = __hfma2(W01, *reinterpret_cast<__half2*>(&q01.y), r);
            r = __hfma2(W10, *reinterpret_cast<__half2*>(&q10.y), r);
            r = __hfma2(W11, *reinterpret_cast<__half2*>(&q11.y), r);
            res.y = *reinterpret_cast<uint32_t*>(&r);
        }
        {
            __half2 r = __hmul2(W00, *reinterpret_cast<__half2*>(&q00.z));
            r = __hfma2(W01, *reinterpret_cast<__half2*>(&q01.z), r);
            r = __hfma2(W10, *reinterpret_cast<__half2*>(&q10.z), r);
            r = __hfma2(W11, *reinterpret_cast<__half2*>(&q11.z), r);
            res.z = *reinterpret_cast<uint32_t*>(&r);
        }
        {
            __half2 r = __hmul2(W00, *reinterpret_cast<__half2*>(&q00.w));
            r = __hfma2(W01, *reinterpret_cast<__half2*>(&q01.w), r);
            r = __hfma2(W10, *reinterpret_cast<__half2*>(&q10.w), r);
            r = __hfma2(W11, *reinterpret_cast<__half2*>(&q11.w), r);
            res.w = *reinterpret_cast<uint32_t*>(&r);
        }

        if (valid) {
            *reinterpret_cast<uint4*>(
                g_A + (size_t)(m0 + ii) * KDIM + k * 128 + lane8 * 8) = res;
        }
    }
}

// ---------------------------------------------------------------------------
// Kernel 4: GEMM — CTA tile 256x128, 8 warps (4m x 2n, warp 64x64), 117 CTAs.
// Single wave, 1 CTA/SM, K-chunk 64, 3-stage cp.async (48KB/stage).
// Per chunk: tensor 2048 cyc vs LDS ~1400 cyc -> tensor-bound.
// ---------------------------------------------------------------------------
#define STAGE_BYTES 49152         // A 32KB + B 16KB
#define GEMM_SMEM   147456        // 3 stages; epilogue so[256][129]=129KB fits

__global__ void gemm_kernel(const float* __restrict__ bias,
                            float* __restrict__ out) {
    extern __shared__ char smem[];
    const uint32_t smem_base = smem_to_u32(smem);
    const int tid  = threadIdx.x;
    const int wid  = tid >> 5;
    const int lane = tid & 31;
    const int m0   = blockIdx.x * 256;
    const int m_warp = (wid >> 1) * 64;   // 0,64,128,192
    const int n_warp = (wid & 1) * 64;    // 0,64

    float acc[4][8][4];
#pragma unroll
    for (int i = 0; i < 4; i++)
#pragma unroll
        for (int j = 0; j < 8; j++)
#pragma unroll
            for (int r = 0; r < 4; r++) acc[i][j][r] = 0.f;

    auto load_chunk = [&](int kc, int s) {
        uint32_t base = smem_base + s * STAGE_BYTES;
        // A: 256 rows x 64 halves = 2048 segs
#pragma unroll
        for (int i = 0; i < 8; i++) {
            int sidx = tid + i * 256;
            int row  = sidx >> 3;
            int cj   = sidx & 7;
            uint32_t off = (uint32_t)(row * 128 + ((cj ^ (row & 7)) << 4));
            cp_async16(base + off,
                       g_A + (size_t)(m0 + row) * KDIM + kc * 64 + cj * 8);
        }
        // B: 128 rows x 64 halves = 1024 segs
#pragma unroll
        for (int i = 0; i < 4; i++) {
            int sidx = tid + i * 256;
            int row  = sidx >> 3;
            int cj   = sidx & 7;
            uint32_t off = (uint32_t)(row * 128 + ((cj ^ (row & 7)) << 4));
            cp_async16(base + 32768 + off,
                       g_W2 + (size_t)row * KDIM + kc * 64 + cj * 8);
        }
        CP_COMMIT();
    };

    load_chunk(0, 0);
    load_chunk(1, 1);

    int s = 0;
    for (int kc = 0; kc < NCHUNK; ++kc) {
        if (kc == NCHUNK - 1) { CP_WAIT0(); } else { CP_WAIT1(); }
        __syncthreads();
        if (kc + 2 < NCHUNK) {
            int s2 = s + 2; if (s2 >= 3) s2 -= 3;
            load_chunk(kc + 2, s2);
        }

        uint32_t aBase = smem_base + s * STAGE_BYTES;
        uint32_t bBase = aBase + 32768;
#pragma unroll
        for (int ks = 0; ks < 4; ++ks) {
            uint32_t afrag[4][4];
#pragma unroll
            for (int mi = 0; mi < 4; mi++) {
                int row = m_warp + mi * 16 + (lane & 15);
                int ch  = 2 * ks + (lane >> 4);
                ldmatrix_x4(afrag[mi], aBase + row * 128 + ((ch ^ (row & 7)) << 4));
            }
            uint32_t bfrag[8][2];
#pragma unroll
            for (int nh = 0; nh < 4; nh++) {
                int row = n_warp + nh * 16 + ((lane >> 4) << 3) + (lane & 7);
                int ch  = 2 * ks + ((lane >> 3) & 1);
                uint32_t r4[4];
                ldmatrix_x4(r4, bBase + row * 128 + ((ch ^ (row & 7)) << 4));
                bfrag[nh * 2][0]     = r4[0];
                bfrag[nh * 2][1]     = r4[1];
                bfrag[nh * 2 + 1][0] = r4[2];
                bfrag[nh * 2 + 1][1] = r4[3];
            }
#pragma unroll
            for (int mi = 0; mi < 4; mi++)
#pragma unroll
                for (int ni = 0; ni < 8; ni++)
                    mma16816(acc[mi][ni], afrag[mi], bfrag[ni]);
        }
        if (++s == 3) s = 0;
    }

    // ---- epilogue: stage 256x128 tile in smem [256][129], coalesced writes
    __syncthreads();
    float* so = reinterpret_cast<float*>(smem);
#pragma unroll
    for (int mi = 0; mi < 4; mi++) {
#pragma unroll
        for (int ni = 0; ni < 8; ni++) {
            int r0 = m_warp + mi * 16 + (lane >> 2);
            int c0 = n_warp + ni * 8 + (lane & 3) * 2;
            so[r0 * 129 + c0]           = acc[mi][ni][0];
            so[r0 * 129 + c0 + 1]       = acc[mi][ni][1];
            so[(r0 + 8) * 129 + c0]     = acc[mi][ni][2];
            so[(r0 + 8) * 129 + c0 + 1] = acc[mi][ni][3];
        }
    }
    __syncthreads();

    // thread = M row (256 threads cover rows 0..255); loop over co.
    {
        int m = m0 + tid;
        bool valid = (m < M_TOT);
        int b   = valid ? (m / PIX) : 0;
        int rem = m - b * PIX;
        float* op = out + (size_t)b * (COUT * PIX) + rem;
        const float* srow = so + tid * 129;
#pragma unroll 8
        for (int co = 0; co < COUT; co++) {
            if (valid) op[(size_t)co * PIX] = srow[co] + __ldg(bias + co);
        }
    }
}

// ---------------------------------------------------------------------------
// Launch
// ---------------------------------------------------------------------------
extern "C" void kernel_launch(void* const* d_in, const int* in_sizes, int n_in,
                              void* d_out, int out_size) {
    const float* input  = (const float*)d_in[0];
    const float* offset = (const float*)d_in[1];
    const float* mask   = (const float*)d_in[2];
    const float* weight = (const float*)d_in[3];
    const float* bias   = (const float*)d_in[4];
    float* out = (float*)d_out;

    cudaFuncSetAttribute(gemm_kernel,
                         cudaFuncAttributeMaxDynamicSharedMemorySize, GEMM_SMEM);

    transpose_kernel<<<B_ * H_ * 8, dim3(32, 8)>>>(input);
    prep_weight_kernel<<<(COUT * KDIM + 255) / 256, 256>>>(weight);
    precompute_kernel<<<(NTASK + 255) / 256, 256>>>(offset, mask);
    sample_kernel<<<(M_TOT + 31) / 32, 512>>>();
    gemm_kernel<<<MT, 256, GEMM_SMEM>>>(bias, out);
}